// round 11
// baseline (speedup 1.0000x reference)
#include <cuda_runtime.h>

#define NN 100000
#define EE 1600000
#define FT 96
#define TT 12
#define NB 391    // ceil(NN/256)
#define WXB 12500 // wx role blocks (8 nodes x 32 lanes each)
#define HISTB 6250

typedef unsigned long long u64;

// ---------------- scratch (device globals; no runtime allocation) ----------------
__device__ __align__(16) float g_wx[(size_t)NN * FT];   // weighted features [n][96]
__device__ __align__(16) float g_agg[(size_t)NN * FT];  // aggregated features [n][96]
__device__ float g_dis[NN];
__device__ float g_wdeg[NN];              // weighted in-degree (excl. self); zeroed after use
__device__ int   g_cnt[NN];               // in-edge counts; zeroed after use
__device__ int   g_off[NN + 1];           // CSR offsets
__device__ int   g_cur[NN];               // scatter cursors
__device__ int   g_bsum[NB];              // block sums for scan
__device__ u64   g_sSN[EE];               // packed (src, norm) bucketed by dst
__device__ float g_M[3 * 8 * 32];         // fused input-projection weights z,r,h
__device__ float g_gb[3 * 32];            // fused biases
__device__ float g_probs[TT];             // softmax(att)

__device__ __forceinline__ float sigf(float x) { return 1.0f / (1.0f + __expf(-x)); }

// ---------------- fused front-end: wx | hist | precompute (block roles) ----------------
__global__ void k_front(const float* __restrict__ x, const float* __restrict__ mlp_w,
                        const float* __restrict__ mlp_b,
                        const int* __restrict__ ei, const float* __restrict__ ew,
                        const float* czw, const float* czb, const float* lzw, const float* lzb,
                        const float* crw, const float* crb, const float* lrw, const float* lrb,
                        const float* chw, const float* chb, const float* lhw, const float* lhb,
                        const float* att)
{
    __shared__ float sW[TT * FT];  // wx role only
    __shared__ float sB[TT];
    int b = blockIdx.x;
    int tid = threadIdx.x;  // 256

    if (b < WXB) {
        // ---- wx role: wx = x * sigmoid(x_flat @ mlp_w + mlp_b) ----
        for (int i = tid; i < TT * FT; i += 256) {
            int t = i / FT, j = i % FT;
            sW[i] = mlp_w[j * TT + t];
        }
        if (tid < TT) sB[tid] = mlp_b[tid];
        __syncthreads();

        int n = b * 8 + (tid >> 5);
        if (n < NN) {
            int lane = tid & 31;
            const float* xr = x + (size_t)n * FT;
            float x0 = xr[lane], x1 = xr[lane + 32], x2 = xr[lane + 64];

            float p[TT];
#pragma unroll
            for (int t = 0; t < TT; t++)
                p[t] = x0 * sW[t * FT + lane] + x1 * sW[t * FT + lane + 32] + x2 * sW[t * FT + lane + 64];
#pragma unroll
            for (int off = 16; off; off >>= 1) {
#pragma unroll
                for (int t = 0; t < TT; t++) p[t] += __shfl_xor_sync(0xffffffffu, p[t], off);
            }
            float* wr = g_wx + (size_t)n * FT;
            int j0 = lane % 12, j1 = (lane + 32) % 12, j2 = (lane + 64) % 12;
            wr[lane]      = x0 * sigf(p[j0] + sB[j0]);
            wr[lane + 32] = x1 * sigf(p[j1] + sB[j1]);
            wr[lane + 64] = x2 * sigf(p[j2] + sB[j2]);
        }
    } else if (b < WXB + HISTB) {
        // ---- hist role: in-edge count + weighted degree ----
        int e = (b - WXB) * 256 + tid;
        if (e < EE) {
            int d = ei[EE + e];
            atomicAdd(&g_cnt[d], 1);
            atomicAdd(&g_wdeg[d], ew[e]);
        }
    } else {
        // ---- precompute role: fused weights + softmax(att) ----
        int f = tid >> 5, l = tid & 31;
#pragma unroll
        for (int g = 0; g < 3; g++) {
            const float* CW = (g == 0) ? czw : (g == 1) ? crw : chw;
            const float* CB = (g == 0) ? czb : (g == 1) ? crb : chb;
            const float* LW = (g == 0) ? lzw : (g == 1) ? lrw : lhw;
            const float* LB = (g == 0) ? lzb : (g == 1) ? lrb : lhb;
            float m = 0.f;
            for (int k = 0; k < 32; k++) m += CW[f * 32 + k] * LW[k * 32 + l];
            g_M[g * 256 + f * 32 + l] = m;
            if (f == 0) {
                float bb = LB[l];
                for (int k = 0; k < 32; k++) bb += CB[k] * LW[k * 32 + l];
                g_gb[g * 32 + l] = bb;
            }
        }
        if (tid < TT) {
            float mx = -1e30f;
            for (int t = 0; t < TT; t++) mx = fmaxf(mx, att[t]);
            float s = 0.f;
            for (int t = 0; t < TT; t++) s += __expf(att[t] - mx);
            g_probs[tid] = __expf(att[tid] - mx) / s;
        }
    }
}

// ---------------- scan stage 1: per-block sums of cnt ----------------
__global__ void k_scan1()
{
    __shared__ int s[256];
    int t = threadIdx.x;
    int n = blockIdx.x * 256 + t;
    int v = (n < NN) ? g_cnt[n] : 0;
    s[t] = v; __syncthreads();
#pragma unroll
    for (int o = 128; o; o >>= 1) {
        if (t < o) s[t] += s[t + o];
        __syncthreads();
    }
    if (t == 0) g_bsum[blockIdx.x] = s[0];
}

// ---------------- scan stage 2+3 merged: offsets/cursors; dis; reset cnt/wdeg ----------------
// Each block warp-scans all NB block sums itself (kills the separate scan2 kernel).
__global__ void k_scan23()
{
    __shared__ int s[256];
    __shared__ int sbp;  // this block's exclusive prefix
    int t = threadIdx.x;
    int lane = t & 31;

    if (t < 32) {
        // warp 0: exclusive prefix of g_bsum[0..blockIdx.x)
        int carry = 0;
        int myb = blockIdx.x;
        for (int c = 0; c < NB; c += 32) {
            int i = c + lane;
            int v = (i < NB) ? g_bsum[i] : 0;
            int x = v;  // inclusive warp scan
#pragma unroll
            for (int o = 1; o < 32; o <<= 1) {
                int y = __shfl_up_sync(0xffffffffu, x, o);
                if (lane >= o) x += y;
            }
            int total = __shfl_sync(0xffffffffu, x, 31);
            if (i == myb) sbp = carry + x - v;  // exclusive
            carry += total;
        }
    }

    int n = blockIdx.x * 256 + t;
    int v = (n < NN) ? g_cnt[n] : 0;
    s[t] = v; __syncthreads();  // also publishes sbp
#pragma unroll
    for (int o = 1; o < 256; o <<= 1) {
        int x = (t >= o) ? s[t - o] : 0;
        __syncthreads();
        s[t] += x;
        __syncthreads();
    }
    if (n < NN) {
        int off = sbp + s[t] - v;
        g_off[n] = off;
        g_cur[n] = off;
        g_dis[n] = rsqrtf(g_wdeg[n] + 1.0f);
        g_cnt[n] = 0;     // zero-after-use: ready for next graph replay
        g_wdeg[n] = 0.f;
    }
    if (n == 0) g_off[NN] = EE;
}

// ---------------- scatter edges into dst-buckets: packed (src, norm) ----------------
__global__ void k_scatter(const int* __restrict__ ei, const float* __restrict__ ew)
{
    int e = blockIdx.x * 256 + threadIdx.x;
    if (e >= EE) return;
    int s = ei[e], d = ei[EE + e];
    float nm = g_dis[s] * ew[e] * g_dis[d];
    int p = atomicAdd(&g_cur[d], 1);
    g_sSN[p] = ((u64)(unsigned)s) | ((u64)__float_as_uint(nm) << 32);
}

// ---------------- gather: agg[n] = self + sum in-edges; float4 (24 active lanes) ----------------
// Warp per node; lanes 0-23 each own one float4 chunk of the 96-float row.
// Per edge: 1 LDG.128 + 2 SHFL + 4 FFMA (vs 3 LDG.32 + 2 SHFL + 3 FFMA before).
__global__ void k_gather()
{
    int n = blockIdx.x * 8 + (threadIdx.x >> 5);
    if (n >= NN) return;
    int lane = threadIdx.x & 31;
    int beg = g_off[n], end = g_off[n + 1];
    float ds = g_dis[n];
    float nmself = ds * ds;  // self-loop norm = 1/deg
    bool act = lane < 24;

    const float4* wx4 = (const float4*)g_wx;
    float4 acc = make_float4(0.f, 0.f, 0.f, 0.f);
    if (act) {
        float4 w = wx4[(size_t)n * 24 + lane];
        acc.x = nmself * w.x; acc.y = nmself * w.y;
        acc.z = nmself * w.z; acc.w = nmself * w.w;
    }

    for (int b = beg; b < end; b += 32) {
        int m = end - b; if (m > 32) m = 32;
        u64 v = (b + lane < end) ? g_sSN[b + lane] : 0ull;  // coalesced LDG.64, all 32 lanes
        unsigned vlo = (unsigned)(v & 0xffffffffu);
        unsigned vhi = (unsigned)(v >> 32);
#pragma unroll 4
        for (int i = 0; i < m; i++) {
            int s = (int)__shfl_sync(0xffffffffu, vlo, i);
            float nm = __uint_as_float(__shfl_sync(0xffffffffu, vhi, i));
            if (act) {
                float4 w = wx4[(size_t)s * 24 + lane];
                acc.x += nm * w.x; acc.y += nm * w.y;
                acc.z += nm * w.z; acc.w += nm * w.w;
            }
        }
    }
    if (act) ((float4*)g_agg)[(size_t)n * 24 + lane] = acc;
}

// ---------------- per-node GRU recurrence + output head (proven scalar version) ----------------
__global__ void __launch_bounds__(128) k_gru(const float* __restrict__ lzw, const float* __restrict__ lrw,
                                             const float* __restrict__ lhw, const float* __restrict__ out_w,
                                             const float* __restrict__ out_b, float* __restrict__ out)
{
    __shared__ float sM[3 * 8 * 32];    // fused input projections (z,r,h)
    __shared__ float sW2[3 * 32 * 32];  // H-projections (z,r,h)
    __shared__ float sb[3 * 32];        // fused biases
    __shared__ float sOw[32 * TT];
    __shared__ float sOb[TT];
    __shared__ float sP[TT];
    __shared__ float sA[32 * 100];      // 32-node agg tile (pad 100)

    int tid = threadIdx.x;  // 128
    for (int i = tid; i < 768; i += 128) sM[i] = g_M[i];
    for (int i = tid; i < 1024; i += 128) {
        sW2[i]        = lzw[1024 + i];
        sW2[1024 + i] = lrw[1024 + i];
        sW2[2048 + i] = lhw[1024 + i];
    }
    for (int i = tid; i < 96; i += 128) sb[i] = g_gb[i];
    for (int i = tid; i < 32 * TT; i += 128) sOw[i] = out_w[i];
    if (tid < TT) { sOb[tid] = out_b[tid]; sP[tid] = g_probs[tid]; }

    int base = blockIdx.x * 32;
    for (int i = tid; i < 32 * FT; i += 128) {
        int nl = i / FT, j = i % FT;
        sA[nl * 100 + j] = g_agg[(size_t)(base + nl) * FT + j];
    }
    __syncthreads();

    int lane = tid & 31;
    int q = lane & 3;           // quad slot -> channel block
    int c0 = q * 8;             // first owned channel
    int nl = tid >> 2;          // local node (0..31)
    int qbase = lane & ~3;
    const float* aRow = sA + nl * 100;

    float H[8], Ha[8];
#pragma unroll
    for (int j = 0; j < 8; j++) { H[j] = 0.f; Ha[j] = 0.f; }

#pragma unroll 1
    for (int t = 0; t < TT; t++) {
        float a[8];
#pragma unroll
        for (int f = 0; f < 8; f++) a[f] = aRow[f * TT + t];

        // ---- Z and R gates together (both use old H -> share shuffles) ----
        float z[8], r[8];
#pragma unroll
        for (int j = 0; j < 8; j++) { z[j] = sb[c0 + j]; r[j] = sb[32 + c0 + j]; }
#pragma unroll
        for (int f = 0; f < 8; f++) {
            float af = a[f];
#pragma unroll
            for (int j = 0; j < 8; j++) {
                z[j] += af * sM[f * 32 + c0 + j];
                r[j] += af * sM[256 + f * 32 + c0 + j];
            }
        }
#pragma unroll
        for (int k = 0; k < 32; k++) {
            float hk = __shfl_sync(0xffffffffu, H[k & 7], qbase | (k >> 3));
#pragma unroll
            for (int j = 0; j < 8; j++) {
                z[j] += hk * sW2[k * 32 + c0 + j];
                r[j] += hk * sW2[1024 + k * 32 + c0 + j];
            }
        }
#pragma unroll
        for (int j = 0; j < 8; j++) r[j] = sigf(r[j]) * H[j];  // r becomes H*R

        // ---- candidate gate (uses H*R) ----
        float hc[8];
#pragma unroll
        for (int j = 0; j < 8; j++) hc[j] = sb[64 + c0 + j];
#pragma unroll
        for (int f = 0; f < 8; f++) {
            float af = a[f];
#pragma unroll
            for (int j = 0; j < 8; j++) hc[j] += af * sM[512 + f * 32 + c0 + j];
        }
#pragma unroll
        for (int k = 0; k < 32; k++) {
            float hrk = __shfl_sync(0xffffffffu, r[k & 7], qbase | (k >> 3));
#pragma unroll
            for (int j = 0; j < 8; j++) hc[j] += hrk * sW2[2048 + k * 32 + c0 + j];
        }

        float pt = sP[t];
#pragma unroll
        for (int j = 0; j < 8; j++) {
            float zz = sigf(z[j]);
            float ht = tanhf(hc[j]);
            H[j] = zz * H[j] + (1.0f - zz) * ht;
            Ha[j] += pt * H[j];
        }
    }

    // ---- output head: relu(Ha) @ out_w + out_b, quad-reduced, smem-staged store ----
#pragma unroll
    for (int j = 0; j < 8; j++) Ha[j] = fmaxf(Ha[j], 0.f);
    float o[TT];
#pragma unroll
    for (int t = 0; t < TT; t++) {
        float acc = 0.f;
#pragma unroll
        for (int j = 0; j < 8; j++) acc += Ha[j] * sOw[(c0 + j) * TT + t];
        acc += __shfl_xor_sync(0xffffffffu, acc, 1);
        acc += __shfl_xor_sync(0xffffffffu, acc, 2);
        o[t] = acc + sOb[t];
    }
    __syncthreads();  // done reading sA -> reuse as output stage
    if (q == 0) {
#pragma unroll
        for (int t = 0; t < TT; t++) sA[nl * 13 + t] = o[t];
    }
    __syncthreads();
    for (int i = tid; i < 32 * TT; i += 128) {
        int row = i / TT, c = i % TT;
        out[(size_t)(base + row) * TT + c] = sA[row * 13 + c];
    }
}

// ---------------- launch ----------------
extern "C" void kernel_launch(void* const* d_in, const int* in_sizes, int n_in,
                              void* d_out, int out_size)
{
    const float* x     = (const float*)d_in[0];
    const int*   ei    = (const int*)d_in[1];
    const float* ew    = (const float*)d_in[2];
    const float* mlp_w = (const float*)d_in[3];
    const float* mlp_b = (const float*)d_in[4];
    const float* att   = (const float*)d_in[5];
    const float* czw   = (const float*)d_in[6];
    const float* czb   = (const float*)d_in[7];
    const float* lzw   = (const float*)d_in[8];
    const float* lzb   = (const float*)d_in[9];
    const float* crw   = (const float*)d_in[10];
    const float* crb   = (const float*)d_in[11];
    const float* lrw   = (const float*)d_in[12];
    const float* lrb   = (const float*)d_in[13];
    const float* chw   = (const float*)d_in[14];
    const float* chb   = (const float*)d_in[15];
    const float* lhw   = (const float*)d_in[16];
    const float* lhb   = (const float*)d_in[17];
    const float* ow    = (const float*)d_in[18];
    const float* ob    = (const float*)d_in[19];
    float* out = (float*)d_out;

    k_front<<<WXB + HISTB + 1, 256>>>(x, mlp_w, mlp_b, ei, ew,
                                      czw, czb, lzw, lzb, crw, crb, lrw, lrb,
                                      chw, chb, lhw, lhb, att);
    k_scan1<<<NB, 256>>>();
    k_scan23<<<NB, 256>>>();
    k_scatter<<<(EE + 255) / 256, 256>>>(ei, ew);
    k_gather<<<(NN + 7) / 8, 256>>>();
    k_gru<<<(NN * 4) / 128, 128>>>(lzw, lrw, lhw, ow, ob, out);
}